// round 12
// baseline (speedup 1.0000x reference)
#include <cuda_runtime.h>
#include <cstdint>

#define TB     256
#define VV     32000
#define HALF   16000
#define NQH    (HALF/4)
#define NROWS  4096
#define KSEL   100
#define NK2    (2*KSEL)
#define CAP    768
#define TERM   512
#define L0     2.25f
#define HB     32
#define NEG_INF (-3.402823466e38f)
#define POS_INF ( 3.402823466e38f)

struct SmemH {
  float    cv[CAP];
  unsigned ci[CAP];
  unsigned long long keys[CAP];
  float    red[16], redb[16];
  unsigned bins[16];
  unsigned hbins[HB];
  unsigned cand_cnt, sub_cnt;
  float    ctrl_H, ctrl_w, ctrl_L;
  unsigned ctrl_CH, ctrl_done;
  unsigned thr_bin;
  float    hist_L, hist_inv;
  unsigned flag;
};

__device__ ulonglong2 g_pack[NROWS][NK2];   // {key, sv bits}
__device__ float    g_ls[NROWS][2];
__device__ float    g_ce[NROWS];
__device__ float    g_kl[NROWS];
__device__ int      g_valid[NROWS];
__device__ unsigned g_arrive[NROWS];        // zero-init; second arriver resets
__device__ unsigned g_done;                 // zero-init; last block resets

__device__ __forceinline__ unsigned f2k(float x){
  unsigned u = __float_as_uint(x);
  return (u & 0x80000000u) ? ~u : (u | 0x80000000u);
}
__device__ __forceinline__ float k2f(unsigned k){
  unsigned u = (k & 0x80000000u) ? (k & 0x7FFFFFFFu) : ~k;
  return __uint_as_float(u);
}
__device__ __forceinline__ unsigned atomAddRelease(unsigned* p, unsigned v){
  unsigned r;
  asm volatile("atom.add.release.gpu.u32 %0, [%1], %2;" : "=r"(r) : "l"(p), "r"(v) : "memory");
  return r;
}
__device__ __forceinline__ unsigned atomAddAcqRel(unsigned* p, unsigned v){
  unsigned r;
  asm volatile("atom.add.acq_rel.gpu.u32 %0, [%1], %2;" : "=r"(r) : "l"(p), "r"(v) : "memory");
  return r;
}

__device__ __forceinline__ void exp2acc(float a, float b, unsigned long long& acc,
                                        unsigned long long l2e2){
  unsigned long long in, sc, rp;
  float x0, x1, r0, r1;
  asm("mov.b64 %0, {%1, %2};"     : "=l"(in) : "f"(a), "f"(b));
  asm("mul.rn.f32x2 %0, %1, %2;"  : "=l"(sc) : "l"(in), "l"(l2e2));
  asm("mov.b64 {%0, %1}, %2;"     : "=f"(x0), "=f"(x1) : "l"(sc));
  asm("ex2.approx.f32 %0, %1;"    : "=f"(r0) : "f"(x0));
  asm("ex2.approx.f32 %0, %1;"    : "=f"(r1) : "f"(x1));
  asm("mov.b64 %0, {%1, %2};"     : "=l"(rp) : "f"(r0), "f"(r1));
  asm("add.rn.f32x2 %0, %1, %2;"  : "=l"(acc) : "l"(acc), "l"(rp));
}

__global__ void __launch_bounds__(TB, 6)
half_kernel(const float* __restrict__ student,
            const float* __restrict__ teacher,
            const int*   __restrict__ labels32,
            float* __restrict__ out, int out_size){
  __shared__ SmemH smv;
  SmemH* sm = &smv;
  const int tid  = threadIdx.x;
  const int lane = tid & 31, w5 = tid >> 5;
  const int row  = blockIdx.x >> 1;
  const int half = blockIdx.x & 1;
  const int base = half * HALF;
  const size_t rowbase = (size_t)row * VV;

  if (tid == 0){
    sm->cand_cnt = 0; sm->ctrl_done = 0; sm->sub_cnt = 0;
    sm->hist_L = L0; sm->hist_inv = (float)HB / 2.5f;   // fixed scale [2.25, 4.75)
  }
  if (tid < HB) sm->hbins[tid] = 0;
  __syncthreads();

  const float4* srow = reinterpret_cast<const float4*>(student + rowbase + base);
  const float4* trow = reinterpret_cast<const float4*>(teacher + rowbase + base);

  unsigned long long l2e2;
  {
    const float l2e = 1.4426950408889634f;
    asm("mov.b64 %0, {%1, %1};" : "=l"(l2e2) : "f"(l2e));
  }
  const float hinv0 = (float)HB / 2.5f;

  // ---- single one-touch streaming pass; candidates + histogram inline ----
  unsigned long long acc01 = 0ull, acc23 = 0ull;
  int i = tid;
  for (; i + TB < NQH; i += 2*TB){
    float4 sA = __ldg(srow + i);
    float4 tA = __ldg(trow + i);
    float4 sB = __ldg(srow + i + TB);
    float4 tB = __ldg(trow + i + TB);
    exp2acc(sA.x, sA.y, acc01, l2e2);
    exp2acc(sA.z, sA.w, acc23, l2e2);
    exp2acc(sB.x, sB.y, acc01, l2e2);
    exp2acc(sB.z, sB.w, acc23, l2e2);
    float mA = fmaxf(fmaxf(tA.x, tA.y), fmaxf(tA.z, tA.w));
    float mB = fmaxf(fmaxf(tB.x, tB.y), fmaxf(tB.z, tB.w));
    if (fmaxf(mA, mB) >= L0){
      #pragma unroll
      for (int e = 0; e < 8; e++){
        float x = (e==0)?tA.x:(e==1)?tA.y:(e==2)?tA.z:(e==3)?tA.w:
                  (e==4)?tB.x:(e==5)?tB.y:(e==6)?tB.z:tB.w;
        if (x >= L0){
          unsigned p = atomicAdd(&sm->cand_cnt, 1u);
          int idx = (e < 4) ? (base + 4*i + e) : (base + 4*(i+TB) + (e-4));
          if (p < CAP){ sm->cv[p] = x; sm->ci[p] = (unsigned)idx; }
          int b = min(HB - 1, (int)((x - L0) * hinv0));
          atomicAdd(&sm->hbins[b], 1u);
        }
      }
    }
  }
  for (; i < NQH; i += TB){
    float4 s = __ldg(srow + i);
    float4 t = __ldg(trow + i);
    exp2acc(s.x, s.y, acc01, l2e2);
    exp2acc(s.z, s.w, acc23, l2e2);
    float mA = fmaxf(fmaxf(t.x, t.y), fmaxf(t.z, t.w));
    if (mA >= L0){
      #pragma unroll
      for (int e = 0; e < 4; e++){
        float x = (e==0)?t.x:(e==1)?t.y:(e==2)?t.z:t.w;
        if (x >= L0){
          unsigned p = atomicAdd(&sm->cand_cnt, 1u);
          if (p < CAP){ sm->cv[p] = x; sm->ci[p] = (unsigned)(base + 4*i + e); }
          int b = min(HB - 1, (int)((x - L0) * hinv0));
          atomicAdd(&sm->hbins[b], 1u);
        }
      }
    }
  }
  float u0, u1, u2, u3;
  asm("mov.b64 {%0, %1}, %2;" : "=f"(u0), "=f"(u1) : "l"(acc01));
  asm("mov.b64 {%0, %1}, %2;" : "=f"(u2), "=f"(u3) : "l"(acc23));
  float esum = (u0 + u1) + (u2 + u3);

  #pragma unroll
  for (int o = 16; o; o >>= 1) esum += __shfl_xor_sync(0xffffffffu, esum, o);
  if (lane == 0) sm->red[w5] = esum;
  __syncthreads();
  if (tid == 0){
    float s = 0.f;
    #pragma unroll
    for (int k = 0; k < TB/32; k++) s += sm->red[k];
    g_ls[row][half] = s;
  }
  __syncthreads();

  unsigned hits = sm->cand_cnt;

  // ---- fallback (never on N(0,1) data): exact bracket via global re-reads ----
  if (hits < KSEL || hits > CAP){
    float tmax = NEG_INF, tmin = POS_INF;
    for (int q = tid; q < NQH; q += TB){
      float4 t = __ldg(trow + q);
      tmax = fmaxf(tmax, fmaxf(fmaxf(t.x, t.y), fmaxf(t.z, t.w)));
      tmin = fminf(tmin, fminf(fminf(t.x, t.y), fminf(t.z, t.w)));
    }
    #pragma unroll
    for (int o = 16; o; o >>= 1){
      tmax = fmaxf(tmax, __shfl_xor_sync(0xffffffffu, tmax, o));
      tmin = fminf(tmin, __shfl_xor_sync(0xffffffffu, tmin, o));
    }
    if (lane == 0){ sm->red[w5] = tmax; sm->redb[w5] = tmin; }
    __syncthreads();
    if (tid == 0){
      float M = sm->red[0], mn = sm->redb[0];
      #pragma unroll
      for (int k = 1; k < TB/32; k++){ M = fmaxf(M, sm->red[k]); mn = fminf(mn, sm->redb[k]); }
      float H = M + (fabsf(M) + 1.0f) * 1e-6f;
      float ww = (H - mn) / 15.9f;
      if (ww < 1e-30f) ww = 1e-30f;
      sm->ctrl_H = H; sm->ctrl_w = ww; sm->ctrl_CH = 0;
    }
    for (int iter = 0; iter < 6; iter++){
      __syncthreads();
      if (sm->ctrl_done) break;
      float H = sm->ctrl_H, ww = sm->ctrl_w;
      float invw = 1.0f / ww;
      if (tid < 16) sm->bins[tid] = 0;
      __syncthreads();
      unsigned long long acc0 = 0ull, acc1 = 0ull;
      for (int q = tid; q < NQH; q += TB){
        float4 v = __ldg(trow + q);
        #pragma unroll
        for (int e = 0; e < 4; e++){
          float x = (e==0)?v.x:(e==1)?v.y:(e==2)?v.z:v.w;
          int b = __float2int_rd((H - x) * invw);
          if ((unsigned)b < 8u)        acc0 += 1ull << (b << 3);
          else if ((unsigned)b < 16u)  acc1 += 1ull << ((b - 8) << 3);
        }
      }
      unsigned p0 = (unsigned)acc0, p1 = (unsigned)(acc0 >> 32);
      unsigned p2 = (unsigned)acc1, p3 = (unsigned)(acc1 >> 32);
      unsigned a0 = p0 & 0x00FF00FFu, a1 = (p0 >> 8) & 0x00FF00FFu;
      unsigned a2 = p1 & 0x00FF00FFu, a3 = (p1 >> 8) & 0x00FF00FFu;
      unsigned a4 = p2 & 0x00FF00FFu, a5 = (p2 >> 8) & 0x00FF00FFu;
      unsigned a6 = p3 & 0x00FF00FFu, a7 = (p3 >> 8) & 0x00FF00FFu;
      #pragma unroll
      for (int o = 16; o; o >>= 1){
        a0 += __shfl_xor_sync(0xffffffffu, a0, o);
        a1 += __shfl_xor_sync(0xffffffffu, a1, o);
        a2 += __shfl_xor_sync(0xffffffffu, a2, o);
        a3 += __shfl_xor_sync(0xffffffffu, a3, o);
        a4 += __shfl_xor_sync(0xffffffffu, a4, o);
        a5 += __shfl_xor_sync(0xffffffffu, a5, o);
        a6 += __shfl_xor_sync(0xffffffffu, a6, o);
        a7 += __shfl_xor_sync(0xffffffffu, a7, o);
      }
      if (lane == 0){
        atomicAdd(&sm->bins[0],  a0 & 0xFFFFu); atomicAdd(&sm->bins[2],  a0 >> 16);
        atomicAdd(&sm->bins[1],  a1 & 0xFFFFu); atomicAdd(&sm->bins[3],  a1 >> 16);
        atomicAdd(&sm->bins[4],  a2 & 0xFFFFu); atomicAdd(&sm->bins[6],  a2 >> 16);
        atomicAdd(&sm->bins[5],  a3 & 0xFFFFu); atomicAdd(&sm->bins[7],  a3 >> 16);
        atomicAdd(&sm->bins[8],  a4 & 0xFFFFu); atomicAdd(&sm->bins[10], a4 >> 16);
        atomicAdd(&sm->bins[9],  a5 & 0xFFFFu); atomicAdd(&sm->bins[11], a5 >> 16);
        atomicAdd(&sm->bins[12], a6 & 0xFFFFu); atomicAdd(&sm->bins[14], a6 >> 16);
        atomicAdd(&sm->bins[13], a7 & 0xFFFFu); atomicAdd(&sm->bins[15], a7 >> 16);
      }
      __syncthreads();
      if (tid == 0){
        unsigned CH = sm->ctrl_CH;
        unsigned cum = CH, prev = CH;
        int j = 15;
        for (int b = 0; b < 16; b++){
          prev = cum; cum += sm->bins[b];
          if (cum >= KSEL){ j = b; break; }
        }
        bool tiny = (ww <= (fabsf(H) + 1e-20f) * 1e-7f);
        if (cum <= TERM || tiny || iter == 5){
          sm->ctrl_L = H - (float)(j + 1) * ww - 0.5f * ww;
          sm->ctrl_done = 1;
        } else {
          sm->ctrl_H  = H - (float)j * ww;
          sm->ctrl_CH = prev;
          sm->ctrl_w  = ww * 0.0625f;
        }
      }
    }
    __syncthreads();
    if (tid == 0) sm->cand_cnt = 0;
    __syncthreads();
    float L = sm->ctrl_L;
    for (int q = tid; q < NQH; q += TB){
      float4 v = __ldg(trow + q);
      #pragma unroll
      for (int e = 0; e < 4; e++){
        float x = (e==0)?v.x:(e==1)?v.y:(e==2)?v.z:v.w;
        if (x >= L){
          unsigned p = atomicAdd(&sm->cand_cnt, 1u);
          if (p < CAP){ sm->cv[p] = x; sm->ci[p] = (unsigned)(base + 4*q + e); }
        }
      }
    }
    __syncthreads();
    int candf = (int)sm->cand_cnt; if (candf > CAP) candf = CAP;
    float cmax = NEG_INF;
    for (int c = tid; c < candf; c += TB) cmax = fmaxf(cmax, sm->cv[c]);
    #pragma unroll
    for (int o = 16; o; o >>= 1) cmax = fmaxf(cmax, __shfl_xor_sync(0xffffffffu, cmax, o));
    if (lane == 0) sm->red[w5] = cmax;
    __syncthreads();
    if (tid < HB) sm->hbins[tid] = 0;
    if (tid == 0){
      float M = sm->red[0];
      #pragma unroll
      for (int k = 1; k < TB/32; k++) M = fmaxf(M, sm->red[k]);
      float span = M - L;
      if (span < 1e-20f) span = 1e-20f;
      sm->hist_L = L;
      sm->hist_inv = (float)HB / (span * 1.0001f);
    }
    __syncthreads();
    float hL2 = sm->hist_L, hinv2 = sm->hist_inv;
    for (int c = tid; c < candf; c += TB){
      int b = max(0, min(HB - 1, (int)((sm->cv[c] - hL2) * hinv2)));
      atomicAdd(&sm->hbins[b], 1u);
    }
    __syncthreads();
  }

  int candn = (int)sm->cand_cnt; if (candn > CAP) candn = CAP;

  // ---- suffix-scan histogram -> threshold bin ----
  if (tid == 0){
    unsigned cum = 0; int t = 0;
    for (int b = HB - 1; b >= 0; b--){
      cum += sm->hbins[b];
      if (cum >= KSEL){ t = b; break; }
    }
    sm->thr_bin = (unsigned)t;
  }
  __syncthreads();
  int tbin = (int)sm->thr_bin;
  float hL = sm->hist_L, hinv = sm->hist_inv;

  // ---- compact subset (bin >= tbin) as u64 keys ----
  for (int c = tid; c < candn; c += TB){
    float x = sm->cv[c];
    int b = max(0, min(HB - 1, (int)((x - hL) * hinv)));
    if (b >= tbin){
      unsigned p = atomicAdd(&sm->sub_cnt, 1u);
      sm->keys[p] = ((unsigned long long)f2k(x) << 32) | (unsigned long long)(0xFFFFFFFFu - sm->ci[c]);
    }
  }
  __syncthreads();
  int n2 = (int)sm->sub_cnt;

  // ---- exact top-100 via all-pairs rank on u64 keys (rank-ordered => sorted out) ----
  for (int c = tid; c < n2; c += TB){
    unsigned long long K = sm->keys[c];
    int r = 0;
    #pragma unroll 4
    for (int j = 0; j < n2; j++) r += (int)(sm->keys[j] > K);
    if (r < KSEL){
      unsigned ix = 0xFFFFFFFFu - (unsigned)K;
      float sv = __ldg(student + rowbase + ix);   // L2-hot
      ulonglong2 pk;
      pk.x = K;
      pk.y = (unsigned long long)__float_as_uint(sv);
      g_pack[row][half*KSEL + r] = pk;
    }
  }
  __syncthreads();

  // ---- row arrival (release publishes this block's g_pack/g_ls writes) ----
  if (tid == 0) sm->flag = atomAddRelease(&g_arrive[row], 1u);
  __syncthreads();

  if (sm->flag == 1u){
    // ===== second arriver: inline merge for this row (acquire done via acq_rel read) =====
    if (tid == 0){ (void)atomAddAcqRel(&g_arrive[row], 0u); }   // acquire peer's writes
    __syncthreads();

    if (tid < NK2){
      ulonglong2 e = g_pack[row][tid];
      sm->keys[tid] = e.x;
      sm->cv[tid]   = __uint_as_float((unsigned)e.y);
    }
    __syncthreads();

    bool act = false; float a = NEG_INF, b = NEG_INF;
    if (tid < NK2){
      int h = tid / KSEL, pos = tid % KSEL;
      unsigned long long K = sm->keys[tid];
      const unsigned long long* other = sm->keys + (1 - h) * KSEL;
      int lo = 0, hi = KSEL;
      while (lo < hi){
        int mid = (lo + hi) >> 1;
        if (other[mid] > K) lo = mid + 1; else hi = mid;
      }
      if (pos + lo < KSEL){
        act = true;
        a = k2f((unsigned)(K >> 32)) * 0.2f;
        b = sm->cv[tid] * 0.2f;
      }
    }

    float ma = a, mb = b;
    #pragma unroll
    for (int o = 16; o; o >>= 1){
      ma = fmaxf(ma, __shfl_xor_sync(0xffffffffu, ma, o));
      mb = fmaxf(mb, __shfl_xor_sync(0xffffffffu, mb, o));
    }
    if (lane == 0){ sm->red[w5] = ma; sm->redb[w5] = mb; }
    __syncthreads();
    float maxA = sm->red[0], maxB = sm->redb[0];
    #pragma unroll
    for (int k = 1; k < TB/32; k++){ maxA = fmaxf(maxA, sm->red[k]); maxB = fmaxf(maxB, sm->redb[k]); }
    __syncthreads();

    float eA = act ? __expf(a - maxA) : 0.f;
    float eB = act ? __expf(b - maxB) : 0.f;
    float sA = eA, sB = eB;
    #pragma unroll
    for (int o = 16; o; o >>= 1){
      sA += __shfl_xor_sync(0xffffffffu, sA, o);
      sB += __shfl_xor_sync(0xffffffffu, sB, o);
    }
    if (lane == 0){ sm->red[w5] = sA; sm->redb[w5] = sB; }
    __syncthreads();
    float tsA = 0.f, tsB = 0.f;
    #pragma unroll
    for (int k = 0; k < TB/32; k++){ tsA += sm->red[k]; tsB += sm->redb[k]; }
    float lseA = maxA + __logf(tsA);
    float lseB = maxB + __logf(tsB);
    __syncthreads();

    float term = act ? (__expf(a - lseA) * ((a - lseA) - (b - lseB))) : 0.f;
    #pragma unroll
    for (int o = 16; o; o >>= 1) term += __shfl_xor_sync(0xffffffffu, term, o);
    if (lane == 0) sm->red[w5] = term;
    __syncthreads();

    if (tid == 0){
      float kl = 0.f;
      #pragma unroll
      for (int k = 0; k < TB/32; k++) kl += sm->red[k];

      float lse = __logf(g_ls[row][0] + g_ls[row][1]);
      int v1 = labels32[1], v3 = labels32[3], v5 = labels32[5];
      bool is64 = (v1==0||v1==-1) && (v3==0||v3==-1) && (v5==0||v5==-1);
      long long lab;
      if (is64){
        unsigned lo2 = (unsigned)labels32[2*row];
        int      hi2 = labels32[2*row+1];
        lab = ((long long)hi2 << 32) | (long long)lo2;
      } else {
        lab = (long long)labels32[row];
      }
      int valid = (lab != -100LL);
      float ce = 0.f;
      if (valid){
        float slab = __ldg(student + (size_t)row * VV + (int)lab);
        ce = lse - slab;
      }
      g_ce[row]    = ce;
      g_kl[row]    = valid ? kl : 0.f;
      g_valid[row] = valid;
      g_arrive[row] = 0;   // reset for graph replay (both atomics already done)
    }
    __syncthreads();
  }

  // ---- global arrival; last of 2*NROWS blocks reduces (all merges published) ----
  if (tid == 0) sm->flag = (atomAddAcqRel(&g_done, 1u) == 2u * NROWS - 1u);
  __syncthreads();
  if (!sm->flag) return;

  {
    float ce = 0.f, kl = 0.f; int nv = 0;
    for (int i2 = tid; i2 < NROWS; i2 += TB){ ce += g_ce[i2]; kl += g_kl[i2]; nv += g_valid[i2]; }
    #pragma unroll
    for (int o = 16; o; o >>= 1){
      ce += __shfl_xor_sync(0xffffffffu, ce, o);
      kl += __shfl_xor_sync(0xffffffffu, kl, o);
      nv += __shfl_xor_sync(0xffffffffu, nv, o);
    }
    if (lane == 0){ sm->red[w5] = ce; sm->redb[w5] = kl; sm->bins[w5] = (unsigned)nv; }
    __syncthreads();
    if (tid == 0){
      float tce = 0.f, tkl = 0.f; int tnv = 0;
      #pragma unroll
      for (int k = 0; k < TB/32; k++){ tce += sm->red[k]; tkl += sm->redb[k]; tnv += (int)sm->bins[k]; }
      float nvf = (float)(tnv > 0 ? tnv : 1);
      float cem = tce / nvf;
      float tcs = tkl / nvf * 25.f;                // * TEMPERATURE^2
      if (out_size > 0) out[0] = cem + 10.f * tcs; // + LAMBDA_TCS * tcs
      if (out_size > 1) out[1] = cem;
      if (out_size > 2) out[2] = tcs;
      if (out_size > 3) out[3] = 0.f;
      g_done = 0;                                  // reset for graph replay
    }
    for (int i2 = 4 + tid; i2 < out_size; i2 += TB) out[i2] = 0.f;
  }
}

extern "C" void kernel_launch(void* const* d_in, const int* in_sizes, int n_in,
                              void* d_out, int out_size){
  const float* student  = (const float*)d_in[0];
  const float* teacher  = (const float*)d_in[1];
  const int*   labels32 = (const int*)d_in[2];

  half_kernel<<<NROWS * 2, TB>>>(student, teacher, labels32, (float*)d_out, out_size);
}

// round 13
// speedup vs baseline: 1.0339x; 1.0339x over previous
#include <cuda_runtime.h>
#include <cstdint>

#define TB     256
#define VV     32000
#define HALF   16000
#define NQH    (HALF/4)
#define NROWS  4096
#define KSEL   100
#define NK2    (2*KSEL)
#define CAP    768
#define TERM   512
#define L0     2.25f
#define HB     32
#define MROWS  2
#define MT     64
#define NEG_INF (-3.402823466e38f)
#define POS_INF ( 3.402823466e38f)

struct SmemH {
  unsigned long long keys[CAP];
  unsigned long long keys2[CAP];
  float    red[16], redb[16];
  unsigned bins[16];
  unsigned hbins[HB];
  unsigned cand_cnt, sub_cnt;
  float    ctrl_H, ctrl_w, ctrl_L;
  unsigned ctrl_CH, ctrl_done;
  unsigned thr_bin;
  float    hist_L, hist_inv;
};

__device__ ulonglong2 g_pack[NROWS][NK2];   // {key, sv bits}
__device__ float    g_ls[NROWS][2];
__device__ float4   g_res[NROWS];           // {ce, kl, valid, 0}
__device__ unsigned g_done;                 // zero-init; last merge block resets

__device__ __forceinline__ unsigned f2k(float x){
  unsigned u = __float_as_uint(x);
  return (u & 0x80000000u) ? ~u : (u | 0x80000000u);
}
__device__ __forceinline__ float k2f(unsigned k){
  unsigned u = (k & 0x80000000u) ? (k & 0x7FFFFFFFu) : ~k;
  return __uint_as_float(u);
}
__device__ __forceinline__ unsigned atomAddAcqRel(unsigned* p, unsigned v){
  unsigned r;
  asm volatile("atom.add.acq_rel.gpu.u32 %0, [%1], %2;" : "=r"(r) : "l"(p), "r"(v) : "memory");
  return r;
}

__device__ __forceinline__ void exp2acc(float a, float b, unsigned long long& acc,
                                        unsigned long long l2e2){
  unsigned long long in, sc, rp;
  float x0, x1, r0, r1;
  asm("mov.b64 %0, {%1, %2};"     : "=l"(in) : "f"(a), "f"(b));
  asm("mul.rn.f32x2 %0, %1, %2;"  : "=l"(sc) : "l"(in), "l"(l2e2));
  asm("mov.b64 {%0, %1}, %2;"     : "=f"(x0), "=f"(x1) : "l"(sc));
  asm("ex2.approx.f32 %0, %1;"    : "=f"(r0) : "f"(x0));
  asm("ex2.approx.f32 %0, %1;"    : "=f"(r1) : "f"(x1));
  asm("mov.b64 %0, {%1, %2};"     : "=l"(rp) : "f"(r0), "f"(r1));
  asm("add.rn.f32x2 %0, %1, %2;"  : "=l"(acc) : "l"(acc), "l"(rp));
}

__global__ void __launch_bounds__(TB, 6)
half_kernel(const float* __restrict__ student,
            const float* __restrict__ teacher){
  __shared__ SmemH smv;
  SmemH* sm = &smv;
  const int tid  = threadIdx.x;
  const int lane = tid & 31, w5 = tid >> 5;
  const int row  = blockIdx.x >> 1;
  const int half = blockIdx.x & 1;
  const int base = half * HALF;
  const size_t rowbase = (size_t)row * VV;

  if (tid == 0){
    sm->cand_cnt = 0; sm->ctrl_done = 0; sm->sub_cnt = 0;
    sm->hist_L = L0; sm->hist_inv = (float)HB / 2.5f;   // fixed scale [2.25, 4.75)
  }
  if (tid < HB) sm->hbins[tid] = 0;
  __syncthreads();

  const float4* srow = reinterpret_cast<const float4*>(student + rowbase + base);
  const float4* trow = reinterpret_cast<const float4*>(teacher + rowbase + base);

  unsigned long long l2e2;
  {
    const float l2e = 1.4426950408889634f;
    asm("mov.b64 %0, {%1, %1};" : "=l"(l2e2) : "f"(l2e));
  }
  const float hinv0 = (float)HB / 2.5f;

  // ---- single one-touch streaming pass; u64-key candidates + histogram inline ----
  unsigned long long acc01 = 0ull, acc23 = 0ull;
  int i = tid;
  for (; i + TB < NQH; i += 2*TB){
    float4 sA = __ldg(srow + i);
    float4 tA = __ldg(trow + i);
    float4 sB = __ldg(srow + i + TB);
    float4 tB = __ldg(trow + i + TB);
    exp2acc(sA.x, sA.y, acc01, l2e2);
    exp2acc(sA.z, sA.w, acc23, l2e2);
    exp2acc(sB.x, sB.y, acc01, l2e2);
    exp2acc(sB.z, sB.w, acc23, l2e2);
    float mA = fmaxf(fmaxf(tA.x, tA.y), fmaxf(tA.z, tA.w));
    float mB = fmaxf(fmaxf(tB.x, tB.y), fmaxf(tB.z, tB.w));
    if (fmaxf(mA, mB) >= L0){
      #pragma unroll
      for (int e = 0; e < 8; e++){
        float x = (e==0)?tA.x:(e==1)?tA.y:(e==2)?tA.z:(e==3)?tA.w:
                  (e==4)?tB.x:(e==5)?tB.y:(e==6)?tB.z:tB.w;
        if (x >= L0){
          unsigned p = atomicAdd(&sm->cand_cnt, 1u);
          int idx = (e < 4) ? (base + 4*i + e) : (base + 4*(i+TB) + (e-4));
          if (p < CAP)
            sm->keys[p] = ((unsigned long long)f2k(x) << 32)
                        | (unsigned long long)(0xFFFFFFFFu - (unsigned)idx);
          int b = min(HB - 1, (int)((x - L0) * hinv0));
          atomicAdd(&sm->hbins[b], 1u);
        }
      }
    }
  }
  for (; i < NQH; i += TB){
    float4 s = __ldg(srow + i);
    float4 t = __ldg(trow + i);
    exp2acc(s.x, s.y, acc01, l2e2);
    exp2acc(s.z, s.w, acc23, l2e2);
    float mA = fmaxf(fmaxf(t.x, t.y), fmaxf(t.z, t.w));
    if (mA >= L0){
      #pragma unroll
      for (int e = 0; e < 4; e++){
        float x = (e==0)?t.x:(e==1)?t.y:(e==2)?t.z:t.w;
        if (x >= L0){
          unsigned p = atomicAdd(&sm->cand_cnt, 1u);
          if (p < CAP)
            sm->keys[p] = ((unsigned long long)f2k(x) << 32)
                        | (unsigned long long)(0xFFFFFFFFu - (unsigned)(base + 4*i + e));
          int b = min(HB - 1, (int)((x - L0) * hinv0));
          atomicAdd(&sm->hbins[b], 1u);
        }
      }
    }
  }
  float u0, u1, u2, u3;
  asm("mov.b64 {%0, %1}, %2;" : "=f"(u0), "=f"(u1) : "l"(acc01));
  asm("mov.b64 {%0, %1}, %2;" : "=f"(u2), "=f"(u3) : "l"(acc23));
  float esum = (u0 + u1) + (u2 + u3);

  #pragma unroll
  for (int o = 16; o; o >>= 1) esum += __shfl_xor_sync(0xffffffffu, esum, o);
  if (lane == 0) sm->red[w5] = esum;
  __syncthreads();
  if (tid == 0){
    float s = 0.f;
    #pragma unroll
    for (int k = 0; k < TB/32; k++) s += sm->red[k];
    g_ls[row][half] = s;
  }
  __syncthreads();

  unsigned hits = sm->cand_cnt;

  // ---- fallback (never on N(0,1) data): exact bracket via global re-reads ----
  if (hits < KSEL || hits > CAP){
    float tmax = NEG_INF, tmin = POS_INF;
    for (int q = tid; q < NQH; q += TB){
      float4 t = __ldg(trow + q);
      tmax = fmaxf(tmax, fmaxf(fmaxf(t.x, t.y), fmaxf(t.z, t.w)));
      tmin = fminf(tmin, fminf(fminf(t.x, t.y), fminf(t.z, t.w)));
    }
    #pragma unroll
    for (int o = 16; o; o >>= 1){
      tmax = fmaxf(tmax, __shfl_xor_sync(0xffffffffu, tmax, o));
      tmin = fminf(tmin, __shfl_xor_sync(0xffffffffu, tmin, o));
    }
    if (lane == 0){ sm->red[w5] = tmax; sm->redb[w5] = tmin; }
    __syncthreads();
    if (tid == 0){
      float M = sm->red[0], mn = sm->redb[0];
      #pragma unroll
      for (int k = 1; k < TB/32; k++){ M = fmaxf(M, sm->red[k]); mn = fminf(mn, sm->redb[k]); }
      float H = M + (fabsf(M) + 1.0f) * 1e-6f;
      float ww = (H - mn) / 15.9f;
      if (ww < 1e-30f) ww = 1e-30f;
      sm->ctrl_H = H; sm->ctrl_w = ww; sm->ctrl_CH = 0;
    }
    for (int iter = 0; iter < 6; iter++){
      __syncthreads();
      if (sm->ctrl_done) break;
      float H = sm->ctrl_H, ww = sm->ctrl_w;
      float invw = 1.0f / ww;
      if (tid < 16) sm->bins[tid] = 0;
      __syncthreads();
      unsigned long long acc0 = 0ull, acc1 = 0ull;
      for (int q = tid; q < NQH; q += TB){
        float4 v = __ldg(trow + q);
        #pragma unroll
        for (int e = 0; e < 4; e++){
          float x = (e==0)?v.x:(e==1)?v.y:(e==2)?v.z:v.w;
          int b = __float2int_rd((H - x) * invw);
          if ((unsigned)b < 8u)        acc0 += 1ull << (b << 3);
          else if ((unsigned)b < 16u)  acc1 += 1ull << ((b - 8) << 3);
        }
      }
      unsigned p0 = (unsigned)acc0, p1 = (unsigned)(acc0 >> 32);
      unsigned p2 = (unsigned)acc1, p3 = (unsigned)(acc1 >> 32);
      unsigned a0 = p0 & 0x00FF00FFu, a1 = (p0 >> 8) & 0x00FF00FFu;
      unsigned a2 = p1 & 0x00FF00FFu, a3 = (p1 >> 8) & 0x00FF00FFu;
      unsigned a4 = p2 & 0x00FF00FFu, a5 = (p2 >> 8) & 0x00FF00FFu;
      unsigned a6 = p3 & 0x00FF00FFu, a7 = (p3 >> 8) & 0x00FF00FFu;
      #pragma unroll
      for (int o = 16; o; o >>= 1){
        a0 += __shfl_xor_sync(0xffffffffu, a0, o);
        a1 += __shfl_xor_sync(0xffffffffu, a1, o);
        a2 += __shfl_xor_sync(0xffffffffu, a2, o);
        a3 += __shfl_xor_sync(0xffffffffu, a3, o);
        a4 += __shfl_xor_sync(0xffffffffu, a4, o);
        a5 += __shfl_xor_sync(0xffffffffu, a5, o);
        a6 += __shfl_xor_sync(0xffffffffu, a6, o);
        a7 += __shfl_xor_sync(0xffffffffu, a7, o);
      }
      if (lane == 0){
        atomicAdd(&sm->bins[0],  a0 & 0xFFFFu); atomicAdd(&sm->bins[2],  a0 >> 16);
        atomicAdd(&sm->bins[1],  a1 & 0xFFFFu); atomicAdd(&sm->bins[3],  a1 >> 16);
        atomicAdd(&sm->bins[4],  a2 & 0xFFFFu); atomicAdd(&sm->bins[6],  a2 >> 16);
        atomicAdd(&sm->bins[5],  a3 & 0xFFFFu); atomicAdd(&sm->bins[7],  a3 >> 16);
        atomicAdd(&sm->bins[8],  a4 & 0xFFFFu); atomicAdd(&sm->bins[10], a4 >> 16);
        atomicAdd(&sm->bins[9],  a5 & 0xFFFFu); atomicAdd(&sm->bins[11], a5 >> 16);
        atomicAdd(&sm->bins[12], a6 & 0xFFFFu); atomicAdd(&sm->bins[14], a6 >> 16);
        atomicAdd(&sm->bins[13], a7 & 0xFFFFu); atomicAdd(&sm->bins[15], a7 >> 16);
      }
      __syncthreads();
      if (tid == 0){
        unsigned CH = sm->ctrl_CH;
        unsigned cum = CH, prev = CH;
        int j = 15;
        for (int b = 0; b < 16; b++){
          prev = cum; cum += sm->bins[b];
          if (cum >= KSEL){ j = b; break; }
        }
        bool tiny = (ww <= (fabsf(H) + 1e-20f) * 1e-7f);
        if (cum <= TERM || tiny || iter == 5){
          sm->ctrl_L = H - (float)(j + 1) * ww - 0.5f * ww;
          sm->ctrl_done = 1;
        } else {
          sm->ctrl_H  = H - (float)j * ww;
          sm->ctrl_CH = prev;
          sm->ctrl_w  = ww * 0.0625f;
        }
      }
    }
    __syncthreads();
    if (tid == 0) sm->cand_cnt = 0;
    __syncthreads();
    float L = sm->ctrl_L;
    for (int q = tid; q < NQH; q += TB){
      float4 v = __ldg(trow + q);
      #pragma unroll
      for (int e = 0; e < 4; e++){
        float x = (e==0)?v.x:(e==1)?v.y:(e==2)?v.z:v.w;
        if (x >= L){
          unsigned p = atomicAdd(&sm->cand_cnt, 1u);
          if (p < CAP)
            sm->keys[p] = ((unsigned long long)f2k(x) << 32)
                        | (unsigned long long)(0xFFFFFFFFu - (unsigned)(base + 4*q + e));
        }
      }
    }
    __syncthreads();
    int candf = (int)sm->cand_cnt; if (candf > CAP) candf = CAP;
    float cmax = NEG_INF;
    for (int c = tid; c < candf; c += TB)
      cmax = fmaxf(cmax, k2f((unsigned)(sm->keys[c] >> 32)));
    #pragma unroll
    for (int o = 16; o; o >>= 1) cmax = fmaxf(cmax, __shfl_xor_sync(0xffffffffu, cmax, o));
    if (lane == 0) sm->red[w5] = cmax;
    __syncthreads();
    if (tid < HB) sm->hbins[tid] = 0;
    if (tid == 0){
      float M = sm->red[0];
      #pragma unroll
      for (int k = 1; k < TB/32; k++) M = fmaxf(M, sm->red[k]);
      float span = M - L;
      if (span < 1e-20f) span = 1e-20f;
      sm->hist_L = L;
      sm->hist_inv = (float)HB / (span * 1.0001f);
    }
    __syncthreads();
    float hL2 = sm->hist_L, hinv2 = sm->hist_inv;
    for (int c = tid; c < candf; c += TB){
      float x = k2f((unsigned)(sm->keys[c] >> 32));
      int b = max(0, min(HB - 1, (int)((x - hL2) * hinv2)));
      atomicAdd(&sm->hbins[b], 1u);
    }
    __syncthreads();
  }

  int candn = (int)sm->cand_cnt; if (candn > CAP) candn = CAP;

  // ---- suffix-scan histogram -> threshold bin ----
  if (tid == 0){
    unsigned cum = 0; int t = 0;
    for (int b = HB - 1; b >= 0; b--){
      cum += sm->hbins[b];
      if (cum >= KSEL){ t = b; break; }
    }
    sm->thr_bin = (unsigned)t;
  }
  __syncthreads();
  int tbin = (int)sm->thr_bin;
  float hL = sm->hist_L, hinv = sm->hist_inv;

  // ---- compact subset (bin >= tbin), same binning formula as capture ----
  for (int c = tid; c < candn; c += TB){
    unsigned long long K = sm->keys[c];
    float x = k2f((unsigned)(K >> 32));
    int b = max(0, min(HB - 1, (int)((x - hL) * hinv)));
    if (b >= tbin){
      unsigned p = atomicAdd(&sm->sub_cnt, 1u);
      sm->keys2[p] = K;
    }
  }
  __syncthreads();
  int n2 = (int)sm->sub_cnt;

  // ---- exact top-100 via all-pairs rank on u64 keys (rank-ordered => sorted out) ----
  for (int c = tid; c < n2; c += TB){
    unsigned long long K = sm->keys2[c];
    int r = 0;
    #pragma unroll 4
    for (int j = 0; j < n2; j++) r += (int)(sm->keys2[j] > K);
    if (r < KSEL){
      unsigned ix = 0xFFFFFFFFu - (unsigned)K;
      float sv = __ldg(student + rowbase + ix);   // L2-hot
      ulonglong2 pk;
      pk.x = K;
      pk.y = (unsigned long long)__float_as_uint(sv);
      g_pack[row][half*KSEL + r] = pk;
    }
  }
}

// ---- warp-per-row merge via binary search; 2 rows/block, grid 2048 ----
__global__ void __launch_bounds__(MT)
merge_kernel(const float* __restrict__ student,
             const int*   __restrict__ labels32,
             float* __restrict__ out, int out_size){
  __shared__ unsigned long long ks[MROWS][2][KSEL];
  __shared__ float red2[MROWS], redb2[MROWS];
  __shared__ unsigned rv2[MROWS];
  __shared__ unsigned done_flag;
  const int tid  = threadIdx.x;
  const int lane = tid & 31, wr = tid >> 5;
  const int row  = blockIdx.x * MROWS + wr;

  float svr[7];
  {
    int k = 0;
    for (int j = lane; j < NK2; j += 32, k++){
      ulonglong2 e = g_pack[row][j];
      ks[wr][j / KSEL][j % KSEL] = e.x;
      svr[k] = __uint_as_float((unsigned)e.y);
    }
  }
  __syncwarp();

  float av[7], bv[7];
  int nsel_local = 0;
  {
    int k = 0;
    for (int j = lane; j < NK2; j += 32, k++){
      int h = j / KSEL, pos = j % KSEL;
      unsigned long long K = ks[wr][h][pos];
      const unsigned long long* other = &ks[wr][1 - h][0];
      int lo = 0, hi = KSEL;
      while (lo < hi){
        int mid = (lo + hi) >> 1;
        if (other[mid] > K) lo = mid + 1; else hi = mid;
      }
      if (pos + lo < KSEL){
        av[nsel_local] = k2f((unsigned)(K >> 32)) * 0.2f;
        bv[nsel_local] = svr[k] * 0.2f;
        nsel_local++;
      }
    }
  }

  float ma = NEG_INF, mb = NEG_INF;
  for (int k = 0; k < nsel_local; k++){ ma = fmaxf(ma, av[k]); mb = fmaxf(mb, bv[k]); }
  #pragma unroll
  for (int o = 16; o; o >>= 1){
    ma = fmaxf(ma, __shfl_xor_sync(0xffffffffu, ma, o));
    mb = fmaxf(mb, __shfl_xor_sync(0xffffffffu, mb, o));
  }
  float sA = 0.f, sB = 0.f;
  for (int k = 0; k < nsel_local; k++){ sA += __expf(av[k] - ma); sB += __expf(bv[k] - mb); }
  #pragma unroll
  for (int o = 16; o; o >>= 1){
    sA += __shfl_xor_sync(0xffffffffu, sA, o);
    sB += __shfl_xor_sync(0xffffffffu, sB, o);
  }
  float lseA = ma + __logf(sA);
  float lseB = mb + __logf(sB);
  float term = 0.f;
  for (int k = 0; k < nsel_local; k++){
    float la = av[k] - lseA, lb = bv[k] - lseB;
    term += __expf(la) * (la - lb);
  }
  #pragma unroll
  for (int o = 16; o; o >>= 1) term += __shfl_xor_sync(0xffffffffu, term, o);

  if (lane == 0){
    float lse = __logf(g_ls[row][0] + g_ls[row][1]);
    int v1 = labels32[1], v3 = labels32[3], v5 = labels32[5];
    bool is64 = (v1==0||v1==-1) && (v3==0||v3==-1) && (v5==0||v5==-1);
    long long lab;
    if (is64){
      unsigned lo2 = (unsigned)labels32[2*row];
      int      hi2 = labels32[2*row+1];
      lab = ((long long)hi2 << 32) | (long long)lo2;
    } else {
      lab = (long long)labels32[row];
    }
    int valid = (lab != -100LL);
    float ce = 0.f;
    if (valid){
      float slab = __ldg(student + (size_t)row * VV + (int)lab);
      ce = lse - slab;
    }
    g_res[row] = make_float4(ce, valid ? term : 0.f, valid ? 1.f : 0.f, 0.f);
  }

  // ---- last block reduces everything (release/acquire via acq_rel counter) ----
  __syncthreads();
  if (tid == 0)
    done_flag = (atomAddAcqRel(&g_done, 1u) == (unsigned)(NROWS / MROWS) - 1u);
  __syncthreads();
  if (!done_flag) return;

  float ce = 0.f, kl = 0.f; int nv = 0;
  for (int i2 = tid; i2 < NROWS; i2 += MT){
    float4 r = g_res[i2];
    ce += r.x; kl += r.y; nv += (int)r.z;
  }
  #pragma unroll
  for (int o = 16; o; o >>= 1){
    ce += __shfl_xor_sync(0xffffffffu, ce, o);
    kl += __shfl_xor_sync(0xffffffffu, kl, o);
    nv += __shfl_xor_sync(0xffffffffu, nv, o);
  }
  if (lane == 0){ red2[wr] = ce; redb2[wr] = kl; rv2[wr] = (unsigned)nv; }
  __syncthreads();
  if (tid == 0){
    float tce = 0.f, tkl = 0.f; int tnv = 0;
    #pragma unroll
    for (int k = 0; k < MROWS; k++){ tce += red2[k]; tkl += redb2[k]; tnv += (int)rv2[k]; }
    float nvf = (float)(tnv > 0 ? tnv : 1);
    float cem = tce / nvf;
    float tcs = tkl / nvf * 25.f;                // * TEMPERATURE^2
    if (out_size > 0) out[0] = cem + 10.f * tcs; // + LAMBDA_TCS * tcs
    if (out_size > 1) out[1] = cem;
    if (out_size > 2) out[2] = tcs;
    if (out_size > 3) out[3] = 0.f;
    g_done = 0;                                  // reset for graph replay
  }
  for (int i2 = 4 + tid; i2 < out_size; i2 += MT) out[i2] = 0.f;
}

extern "C" void kernel_launch(void* const* d_in, const int* in_sizes, int n_in,
                              void* d_out, int out_size){
  const float* student  = (const float*)d_in[0];
  const float* teacher  = (const float*)d_in[1];
  const int*   labels32 = (const int*)d_in[2];

  half_kernel<<<NROWS * 2, TB>>>(student, teacher);
  merge_kernel<<<NROWS / MROWS, MT>>>(student, labels32, (float*)d_out, out_size);
}